// round 12
// baseline (speedup 1.0000x reference)
#include <cuda_runtime.h>
#include <cstdint>
#include <math.h>

#define IMG_H 128
#define IMG_W 128
#define HW (IMG_H * IMG_W)
#define B_MAX 4
#define F_MAX 8192
#define N_MAX 4096
#define EPSF 1e-9f
#define BINS 4096

#define NBLK 512
#define NTHR 256
#define SPLIT 2

typedef unsigned long long u64;
typedef unsigned int u32;

// Scratch (allocation-free: __device__ globals)
__device__ float4 g_verts[B_MAX * N_MAX];     // (sx, sy, sz, w)
__device__ u64 g_zbuf[B_MAX * HW];            // (ordered_z << 32) | face_id
__device__ u32 g_fz[B_MAX * F_MAX];           // per-(b,f) ordered-encoded zmin
__device__ u32 g_fbin[B_MAX * F_MAX];         // per-(b,f) depth bin
__device__ u32 g_sorted[B_MAX * F_MAX];       // (b*F+f) sorted front-to-back
__device__ u32 g_hist[BINS];
__device__ u32 g_cursor[BINS];
__device__ u32 g_zlo_u, g_zhi_u;              // ordered-encoded global zmin range

// Grid barrier state (monotonic generation; survives replays harmlessly)
__device__ u32 g_gen = 0;
__device__ u32 g_cnt = 0;

__device__ __forceinline__ u32 ordf(float z) {
    u32 uz = __float_as_uint(z);
    return (uz & 0x80000000u) ? ~uz : (uz | 0x80000000u);
}

// Grid-wide barrier. All NBLK blocks are resident (launch_bounds guarantees
// >=4 blocks/SM; 512 <= 4*148). Release via monotonic generation counter.
__device__ __forceinline__ void gbar() {
    __threadfence();      // release: every thread's prior writes -> L2
    __syncthreads();
    if (threadIdx.x == 0) {
        u32 gen = atomicAdd(&g_gen, 0u);       // read BEFORE arrival
        if (atomicAdd(&g_cnt, 1u) + 1u == (u32)NBLK) {
            atomicExch(&g_cnt, 0u);
            __threadfence();
            atomicAdd(&g_gen, 1u);             // release waiters
        } else {
            while (atomicAdd(&g_gen, 0u) == gen) __nanosleep(64);
        }
    }
    __syncthreads();
}

__global__ __launch_bounds__(NTHR, 4)
void k_render(const float* __restrict__ vertices,
              const float* __restrict__ uv_map,
              const int* __restrict__ faces,
              const float* __restrict__ texture,
              const float* __restrict__ poses,
              float* __restrict__ out,
              int N, int F, int B, int TH, int TW) {
    const int gid = blockIdx.x * NTHR + threadIdx.x;
    const int nth = NBLK * NTHR;
    const int npix = B * HW;
    const int nf = B * F;

    // ---------------- Phase 1: clear + vertex transform ----------------
    for (int i = gid; i < npix; i += nth) g_zbuf[i] = 0xFFFFFFFFFFFFFFFFull;
    for (int i = gid; i < BINS; i += nth) g_hist[i] = 0;
    if (gid == 0) { g_zlo_u = 0xFFFFFFFFu; g_zhi_u = 0u; }

    {
        const double NEAR = 0.1, FAR = 10.0, FOCAL = 140.0;
        const double RIGHT = (IMG_W - 1.0) / 2.0 * NEAR / FOCAL;
        const double TOP = RIGHT * ((double)IMG_H / (double)IMG_W);
        const float p00 = (float)(NEAR / RIGHT);
        const float p11 = (float)(NEAR / TOP);
        const float p22 = (float)(-(FAR + NEAR) / (FAR - NEAR));
        const float p32 = (float)(-2.0 * FAR * NEAR / (FAR - NEAR));

        for (int i = gid; i < B * N; i += nth) {
            int b = i / N;
            int v = i - b * N;
            const float* P = poses + b * 16;
            float C[4][4];
            const float sgn[3] = {1.f, -1.f, -1.f};
#pragma unroll
            for (int r = 0; r < 3; ++r)
#pragma unroll
                for (int c = 0; c < 3; ++c)
                    C[r][c] = sgn[r] * P[r * 4 + c];
            C[0][3] = P[3];
            C[1][3] = -P[7];
            C[2][3] = -P[11];
#pragma unroll
            for (int c = 0; c < 4; ++c) C[3][c] = P[12 + c];

            const float* vp = vertices + ((size_t)b * N + v) * 3;
            float x = vp[0], y = vp[1], z = vp[2];
            float v0 = x * C[0][0] + y * C[0][1] + z * C[0][2] + C[0][3];
            float v1 = x * C[1][0] + y * C[1][1] + z * C[1][2] + C[1][3];
            float v2 = x * C[2][0] + y * C[2][1] + z * C[2][2] + C[2][3];
            float v3 = x * C[3][0] + y * C[3][1] + z * C[3][2] + C[3][3];
            float cx = v0 * p00;
            float cy = v1 * p11;
            float cz = v2 * p22 + v3 * p32;
            float cw = -v2;
            float sx = (cx / cw * 0.5f + 0.5f) * (float)IMG_W;
            float sy = (0.5f - cy / cw * 0.5f) * (float)IMG_H;
            float sz = cz / cw;
            g_verts[b * N + v] = make_float4(sx, sy, sz, cw);
        }
    }
    gbar();

    // ---------------- Phase 2: per-face zmin + global range ----------------
    for (int idx = gid; idx < nf; idx += nth) {
        int b = idx / F;
        int f = idx - b * F;
        int i0 = faces[3 * f + 0];
        int i1 = faces[3 * f + 1];
        int i2 = faces[3 * f + 2];
        float4 v0 = g_verts[b * N + i0];
        float4 v1 = g_verts[b * N + i1];
        float4 v2 = g_verts[b * N + i2];
        u32 e;
        if (v0.w > 1e-6f && v1.w > 1e-6f && v2.w > 1e-6f) {
            float zmn = fminf(v0.z, fminf(v1.z, v2.z));
            e = ordf(zmn);
            atomicMin(&g_zlo_u, e);
            atomicMax(&g_zhi_u, e);
        } else {
            e = 0xFFFFFFFFu;
        }
        g_fz[idx] = e;
    }
    gbar();

    // ---------------- Phase 3: histogram (adaptive range) ----------------
    {
        u32 lo = __ldcg(&g_zlo_u), hi = __ldcg(&g_zhi_u);
        for (int idx = gid; idx < nf; idx += nth) {
            u32 e = g_fz[idx];          // own write (same thread mapping)
            u32 bin;
            if (e == 0xFFFFFFFFu) bin = BINS - 1;
            else if (hi <= lo) bin = 0;
            else {
                u64 d = (u64)(e - lo);
                bin = (u32)((d * (u64)(BINS - 1)) / (u64)(hi - lo));
                if (bin > BINS - 2) bin = BINS - 2;
            }
            g_fbin[idx] = bin;
            atomicAdd(&g_hist[bin], 1u);
        }
    }
    gbar();

    // ---------------- Phase 4: exclusive scan (block 0 only) ----------------
    __shared__ u32 sh[NTHR];
    if (blockIdx.x == 0) {
        int t = threadIdx.x;
        u32 s = 0;
#pragma unroll 4
        for (int j = 0; j < BINS / NTHR; ++j) s += __ldcg(&g_hist[t * (BINS / NTHR) + j]);
        sh[t] = s;
        __syncthreads();
        for (int d = 1; d < NTHR; d <<= 1) {
            u32 v = sh[t];
            u32 w = (t >= d) ? sh[t - d] : 0u;
            __syncthreads();
            sh[t] = v + w;
            __syncthreads();
        }
        u32 run = (t == 0) ? 0u : sh[t - 1];
#pragma unroll 4
        for (int j = 0; j < BINS / NTHR; ++j) {
            u32 hv = __ldcg(&g_hist[t * (BINS / NTHR) + j]);
            g_cursor[t * (BINS / NTHR) + j] = run;
            run += hv;
        }
    }
    gbar();

    // ---------------- Phase 5: scatter into sorted order ----------------
    for (int idx = gid; idx < nf; idx += nth) {
        u32 pos = atomicAdd(&g_cursor[g_fbin[idx]], 1u);
        g_sorted[pos] = (u32)idx;
    }
    gbar();

    // ---------------- Phase 6: raster (front-to-back, R8 numerics) ----------
    {
        int gwarp = gid >> 5;
        int lane = threadIdx.x & 31;
        int totwarps = nth >> 5;
        int nitems = nf * SPLIT;
        for (int wi = gwarp; wi < nitems; wi += totwarps) {
            int slot = wi >> 1;
            int sub = wi & 1;
            int idx = (int)__ldcg(&g_sorted[slot]);
            int b = idx / F;
            int f = idx - b * F;

            int i0 = faces[3 * f + 0];
            int i1 = faces[3 * f + 1];
            int i2 = faces[3 * f + 2];
            float4 v0 = g_verts[b * N + i0];
            float4 v1 = g_verts[b * N + i1];
            float4 v2 = g_verts[b * N + i2];

            if (!(v0.w > 1e-6f && v1.w > 1e-6f && v2.w > 1e-6f)) continue;

            float x0 = v0.x, y0 = v0.y, x1 = v1.x, y1 = v1.y, x2 = v2.x, y2 = v2.y;

            float minx = fminf(x0, fminf(x1, x2));
            float maxx = fmaxf(x0, fmaxf(x1, x2));
            float miny = fminf(y0, fminf(y1, y2));
            float maxy = fmaxf(y0, fmaxf(y1, y2));

            int c0 = max(0, (int)floorf(minx - 0.5f));
            int c1 = min(IMG_W - 1, (int)ceilf(maxx - 0.5f));
            int r0 = max(0, (int)floorf(miny - 0.5f));
            int r1 = min(IMG_H - 1, (int)ceilf(maxy - 0.5f));
            if (c1 < c0 || r1 < r0) continue;

            float dx0 = x2 - x1, dy0 = y2 - y1;
            float dx1 = x0 - x2, dy1 = y0 - y2;
            float dx2 = x1 - x0, dy2 = y1 - y0;
            float z0 = v0.z, z1 = v1.z, z2 = v2.z;

            float zmn = fminf(z0, fminf(z1, z2)) - 1e-5f;
            if (zmn > 1.0f) continue;
            u32 zmn_ord = ordf(zmn);

            u32 W = (u32)(c1 - c0 + 1);
            u32 total = W * (u32)(r1 - r0 + 1);
            u32 m = 0xFFFFFFFFu / W + 1u;

            u64* zb = g_zbuf + b * HW;
            u32 fid = (u32)f;

            for (u32 i = (u32)lane + 32u * (u32)sub; i < total; i += 32u * SPLIT) {
                u32 q = __umulhi(i, m);
                u32 cc = i - q * W;
                int r = r0 + (int)q;
                int c = c0 + (int)cc;
                u64* addr = zb + r * IMG_W + c;
                // stale L1 reads are only larger (monotone decrease) -> safe
                u32 cur_hi = ((const u32*)addr)[1];
                if (zmn_ord > cur_hi) continue;

                float px = (float)c + 0.5f;
                float py = (float)r + 0.5f;
                float e0 = dx0 * (py - y1) - dy0 * (px - x1);
                float e1 = dx1 * (py - y2) - dy1 * (px - x2);
                float e2 = dx2 * (py - y0) - dy2 * (px - x0);
                float area = (e0 + e1) + e2;
                if (fabsf(area) <= EPSF) continue;
                float s = area > 0.f ? 1.f : -1.f;
                if (e0 * s < 0.f || e1 * s < 0.f || e2 * s < 0.f) continue;

                float num = e0 * z0 + e1 * z1;
                num += e2 * z2;
                float z = num / area;   // exact division, matches reference
                if (!(z >= -1.f && z <= 1.f)) continue;

                u32 uz = ordf(z);
                if (uz > cur_hi) continue;
                u64 key = ((u64)uz << 32) | fid;
                atomicMin(addr, key);
            }
        }
    }
    gbar();

    // ---------------- Phase 7: shade + texture ----------------
    for (int p = gid; p < npix; p += nth) {
        int b = p / HW;
        int rc = p - b * HW;
        int r = rc / IMG_W;
        int c = rc - r * IMG_W;

        float o0 = 0.f, o1 = 0.f, o2 = 0.f;
        // MUST bypass L1: this block may hold stale sentinel lines from the
        // clear/raster phases; L2 has the authoritative final keys.
        u64 key = __ldcg(&g_zbuf[p]);
        if (key != 0xFFFFFFFFFFFFFFFFull) {
            int f = (int)(u32)(key & 0xFFFFFFFFull);
            int i0 = faces[3 * f + 0];
            int i1 = faces[3 * f + 1];
            int i2 = faces[3 * f + 2];
            float4 v0 = g_verts[b * N + i0];
            float4 v1 = g_verts[b * N + i1];
            float4 v2 = g_verts[b * N + i2];

            float px = (float)c + 0.5f, py = (float)r + 0.5f;
            float e0 = (v2.x - v1.x) * (py - v1.y) - (v2.y - v1.y) * (px - v1.x);
            float e1 = (v0.x - v2.x) * (py - v2.y) - (v0.y - v2.y) * (px - v2.x);
            float e2 = (v1.x - v0.x) * (py - v0.y) - (v1.y - v0.y) * (px - v0.x);

            float bw0 = e0 / v0.w, bw1 = e1 / v1.w, bw2 = e2 / v2.w;
            float denom = (bw0 + bw1) + bw2;
            if (fabsf(denom) <= EPSF) denom = 1.f;
            float pc0 = bw0 / denom, pc1 = bw1 / denom, pc2 = bw2 / denom;

            float mask = (pc0 + pc1) + pc2;  // color channel 0 is all-ones

            const float* uvb = uv_map + (size_t)b * N * 2;
            float u = pc0 * __ldg(uvb + i0 * 2 + 0) + pc1 * __ldg(uvb + i1 * 2 + 0) + pc2 * __ldg(uvb + i2 * 2 + 0);
            float v = pc0 * __ldg(uvb + i0 * 2 + 1) + pc1 * __ldg(uvb + i1 * 2 + 1) + pc2 * __ldg(uvb + i2 * 2 + 1);

            float fyf = fminf(fmaxf(v, 0.f), 1.f) * (float)TH;
            float fxf = fminf(fmaxf(u, 0.f), 1.f) * (float)TW;
            float fly = floorf(fyf), flx = floorf(fxf);
            float fry = fyf - fly, frx = fxf - flx;
            int iy = (int)fly, ix = (int)flx;
            int iy0 = min(max(iy, 0), TH - 1);
            int iy1 = min(max(iy + 1, 0), TH - 1);
            int ix0 = min(max(ix, 0), TW - 1);
            int ix1 = min(max(ix + 1, 0), TW - 1);

            const float* T = texture + (size_t)b * TH * TW * 3;
            const float* tl = T + ((size_t)iy0 * TW + ix0) * 3;
            const float* tr = T + ((size_t)iy0 * TW + ix1) * 3;
            const float* bl = T + ((size_t)iy1 * TW + ix0) * 3;
            const float* br = T + ((size_t)iy1 * TW + ix1) * 3;

            float wtl = (1.f - frx) * (1.f - fry);
            float wtr = frx * (1.f - fry);
            float wbl = (1.f - frx) * fry;
            float wbr = frx * fry;

            o0 = (__ldg(tl + 0) * wtl + __ldg(tr + 0) * wtr + __ldg(bl + 0) * wbl + __ldg(br + 0) * wbr) * mask;
            o1 = (__ldg(tl + 1) * wtl + __ldg(tr + 1) * wtr + __ldg(bl + 1) * wbl + __ldg(br + 1) * wbr) * mask;
            o2 = (__ldg(tl + 2) * wtl + __ldg(tr + 2) * wtr + __ldg(bl + 2) * wbl + __ldg(br + 2) * wbr) * mask;
        }
        float* op = out + (size_t)p * 3;
        op[0] = o0;
        op[1] = o1;
        op[2] = o2;
    }
}

// ---------------------------------------------------------------------------
// Launch: one persistent kernel, one graph node.
// ---------------------------------------------------------------------------
extern "C" void kernel_launch(void* const* d_in, const int* in_sizes, int n_in,
                              void* d_out, int out_size) {
    const float* vertices = (const float*)d_in[0];
    const float* uv_map   = (const float*)d_in[1];
    const int*   faces    = (const int*)d_in[2];
    const float* texture  = (const float*)d_in[3];
    const float* poses    = (const float*)d_in[4];
    float* out = (float*)d_out;

    int B = in_sizes[4] / 16;
    int N = in_sizes[0] / (3 * B);
    int F = in_sizes[2] / 3;
    long texel = (long)in_sizes[3] / (3L * B);
    int TH = (int)(sqrt((double)texel) + 0.5);
    int TW = TH;

    k_render<<<NBLK, NTHR>>>(vertices, uv_map, faces, texture, poses, out,
                             N, F, B, TH, TW);
}

// round 14
// speedup vs baseline: 1.4488x; 1.4488x over previous
#include <cuda_runtime.h>
#include <cstdint>
#include <math.h>

#define IMG_H 128
#define IMG_W 128
#define HW (IMG_H * IMG_W)
#define B_MAX 4
#define F_MAX 8192
#define N_MAX 4096
#define EPSF 1e-9f
#define BINS 4096

#define PRE_NBLK 256
#define PRE_NTHR 256
#define SPLIT 2

typedef unsigned long long u64;
typedef unsigned int u32;

// Scratch (allocation-free: __device__ globals)
__device__ float4 g_verts[B_MAX * N_MAX];     // (sx, sy, sz, w)
__device__ u64 g_zbuf[B_MAX * HW];            // (ordered_z << 32) | face_id
__device__ u32 g_fz[B_MAX * F_MAX];           // per-(b,f) ordered-encoded zmin
__device__ u32 g_fbin[B_MAX * F_MAX];         // per-(b,f) depth bin
__device__ u32 g_sorted[B_MAX * F_MAX];       // (b*F+f) sorted front-to-back
__device__ u32 g_hist[BINS];
__device__ u32 g_cursor[BINS];
__device__ u32 g_zlo_u, g_zhi_u;              // ordered-encoded global zmin range

// Grid barrier state (monotonic generation; survives graph replays)
__device__ u32 g_gen = 0;
__device__ u32 g_cnt = 0;

__device__ __forceinline__ u32 ordf(float z) {
    u32 uz = __float_as_uint(z);
    return (uz & 0x80000000u) ? ~uz : (uz | 0x80000000u);
}

// Grid-wide barrier for k_pre (PRE_NBLK blocks, all resident: 256 <= 148*2).
__device__ __forceinline__ void gbar() {
    __threadfence();
    __syncthreads();
    if (threadIdx.x == 0) {
        u32 gen = atomicAdd(&g_gen, 0u);
        if (atomicAdd(&g_cnt, 1u) + 1u == (u32)PRE_NBLK) {
            atomicExch(&g_cnt, 0u);
            __threadfence();
            atomicAdd(&g_gen, 1u);
        } else {
            while (atomicAdd(&g_gen, 0u) == gen) __nanosleep(32);
        }
    }
    __syncthreads();
}

// ---------------------------------------------------------------------------
// Kernel 1 (persistent, cheap phases): clear + transform + facez + hist +
// scan + scatter. Low occupancy is fine here — total work is tiny.
// ---------------------------------------------------------------------------
__global__ __launch_bounds__(PRE_NTHR, 2)
void k_pre(const float* __restrict__ vertices,
           const float* __restrict__ poses,
           const int* __restrict__ faces,
           int N, int F, int B) {
    const int gid = blockIdx.x * PRE_NTHR + threadIdx.x;
    const int nth = PRE_NBLK * PRE_NTHR;
    const int npix = B * HW;
    const int nf = B * F;

    // ---- Phase 1: clear + vertex transform ----
    for (int i = gid; i < npix; i += nth) g_zbuf[i] = 0xFFFFFFFFFFFFFFFFull;
    for (int i = gid; i < BINS; i += nth) g_hist[i] = 0;
    if (gid == 0) { g_zlo_u = 0xFFFFFFFFu; g_zhi_u = 0u; }

    {
        const double NEAR = 0.1, FAR = 10.0, FOCAL = 140.0;
        const double RIGHT = (IMG_W - 1.0) / 2.0 * NEAR / FOCAL;
        const double TOP = RIGHT * ((double)IMG_H / (double)IMG_W);
        const float p00 = (float)(NEAR / RIGHT);
        const float p11 = (float)(NEAR / TOP);
        const float p22 = (float)(-(FAR + NEAR) / (FAR - NEAR));
        const float p32 = (float)(-2.0 * FAR * NEAR / (FAR - NEAR));

        for (int i = gid; i < B * N; i += nth) {
            int b = i / N;
            int v = i - b * N;
            const float* P = poses + b * 16;
            float C[4][4];
            const float sgn[3] = {1.f, -1.f, -1.f};
#pragma unroll
            for (int r = 0; r < 3; ++r)
#pragma unroll
                for (int c = 0; c < 3; ++c)
                    C[r][c] = sgn[r] * P[r * 4 + c];
            C[0][3] = P[3];
            C[1][3] = -P[7];
            C[2][3] = -P[11];
#pragma unroll
            for (int c = 0; c < 4; ++c) C[3][c] = P[12 + c];

            const float* vp = vertices + ((size_t)b * N + v) * 3;
            float x = vp[0], y = vp[1], z = vp[2];
            float v0 = x * C[0][0] + y * C[0][1] + z * C[0][2] + C[0][3];
            float v1 = x * C[1][0] + y * C[1][1] + z * C[1][2] + C[1][3];
            float v2 = x * C[2][0] + y * C[2][1] + z * C[2][2] + C[2][3];
            float v3 = x * C[3][0] + y * C[3][1] + z * C[3][2] + C[3][3];
            float cx = v0 * p00;
            float cy = v1 * p11;
            float cz = v2 * p22 + v3 * p32;
            float cw = -v2;
            float sx = (cx / cw * 0.5f + 0.5f) * (float)IMG_W;
            float sy = (0.5f - cy / cw * 0.5f) * (float)IMG_H;
            float sz = cz / cw;
            g_verts[b * N + v] = make_float4(sx, sy, sz, cw);
        }
    }
    gbar();

    // ---- Phase 2: per-face zmin + global range (cross-phase reads via L2) ----
    for (int idx = gid; idx < nf; idx += nth) {
        int b = idx / F;
        int f = idx - b * F;
        int i0 = faces[3 * f + 0];
        int i1 = faces[3 * f + 1];
        int i2 = faces[3 * f + 2];
        const float4* vb = g_verts + b * N;
        float4 v0, v1, v2;
        v0.z = __ldcg(&vb[i0].z); v0.w = __ldcg(&vb[i0].w);
        v1.z = __ldcg(&vb[i1].z); v1.w = __ldcg(&vb[i1].w);
        v2.z = __ldcg(&vb[i2].z); v2.w = __ldcg(&vb[i2].w);
        u32 e;
        if (v0.w > 1e-6f && v1.w > 1e-6f && v2.w > 1e-6f) {
            float zmn = fminf(v0.z, fminf(v1.z, v2.z));
            e = ordf(zmn);
            atomicMin(&g_zlo_u, e);
            atomicMax(&g_zhi_u, e);
        } else {
            e = 0xFFFFFFFFu;
        }
        g_fz[idx] = e;   // same thread re-reads below (self-coherent)
    }
    gbar();

    // ---- Phase 3: histogram (adaptive range) ----
    {
        u32 lo = __ldcg(&g_zlo_u), hi = __ldcg(&g_zhi_u);
        for (int idx = gid; idx < nf; idx += nth) {
            u32 e = g_fz[idx];          // own write (same mapping)
            u32 bin;
            if (e == 0xFFFFFFFFu) bin = BINS - 1;
            else if (hi <= lo) bin = 0;
            else {
                u64 d = (u64)(e - lo);
                bin = (u32)((d * (u64)(BINS - 1)) / (u64)(hi - lo));
                if (bin > BINS - 2) bin = BINS - 2;
            }
            g_fbin[idx] = bin;
            atomicAdd(&g_hist[bin], 1u);
        }
    }
    gbar();

    // ---- Phase 4: exclusive scan over BINS (block 0) ----
    __shared__ u32 sh[PRE_NTHR];
    if (blockIdx.x == 0) {
        int t = threadIdx.x;
        const int PER = BINS / PRE_NTHR;   // 16
        u32 s = 0;
#pragma unroll
        for (int j = 0; j < PER; ++j) s += __ldcg(&g_hist[t * PER + j]);
        sh[t] = s;
        __syncthreads();
        for (int d = 1; d < PRE_NTHR; d <<= 1) {
            u32 v = sh[t];
            u32 w = (t >= d) ? sh[t - d] : 0u;
            __syncthreads();
            sh[t] = v + w;
            __syncthreads();
        }
        u32 run = (t == 0) ? 0u : sh[t - 1];
#pragma unroll
        for (int j = 0; j < PER; ++j) {
            u32 hv = __ldcg(&g_hist[t * PER + j]);
            g_cursor[t * PER + j] = run;
            run += hv;
        }
    }
    gbar();

    // ---- Phase 5: scatter into sorted order (cursor via L2 atomics) ----
    for (int idx = gid; idx < nf; idx += nth) {
        u32 pos = atomicAdd(&g_cursor[g_fbin[idx]], 1u);
        g_sorted[pos] = (u32)idx;
    }
}

// ---------------------------------------------------------------------------
// Kernel 2: raster, front-to-back order, 2 warps/face, 32-bit early-Z prune.
// [R8 verbatim — full-occupancy standalone launch]
// ---------------------------------------------------------------------------
__global__ void k_raster(const int* __restrict__ faces, int N, int F, int B) {
    int gw = (blockIdx.x * blockDim.x + threadIdx.x) >> 5;
    int lane = threadIdx.x & 31;
    int slot = gw >> 1;
    int sub = gw & 1;
    if (slot >= B * F) return;
    int idx = (int)g_sorted[slot];
    int b = idx / F;
    int f = idx - b * F;

    int i0 = faces[3 * f + 0];
    int i1 = faces[3 * f + 1];
    int i2 = faces[3 * f + 2];
    float4 v0 = g_verts[b * N + i0];
    float4 v1 = g_verts[b * N + i1];
    float4 v2 = g_verts[b * N + i2];

    if (!(v0.w > 1e-6f && v1.w > 1e-6f && v2.w > 1e-6f)) return;

    float x0 = v0.x, y0 = v0.y, x1 = v1.x, y1 = v1.y, x2 = v2.x, y2 = v2.y;

    float minx = fminf(x0, fminf(x1, x2));
    float maxx = fmaxf(x0, fmaxf(x1, x2));
    float miny = fminf(y0, fminf(y1, y2));
    float maxy = fmaxf(y0, fmaxf(y1, y2));

    int c0 = max(0, (int)floorf(minx - 0.5f));
    int c1 = min(IMG_W - 1, (int)ceilf(maxx - 0.5f));
    int r0 = max(0, (int)floorf(miny - 0.5f));
    int r1 = min(IMG_H - 1, (int)ceilf(maxy - 0.5f));
    if (c1 < c0 || r1 < r0) return;

    float dx0 = x2 - x1, dy0 = y2 - y1;
    float dx1 = x0 - x2, dy1 = y0 - y2;
    float dx2 = x1 - x0, dy2 = y1 - y0;
    float z0 = v0.z, z1 = v1.z, z2 = v2.z;

    float zmn = fminf(z0, fminf(z1, z2)) - 1e-5f;
    if (zmn > 1.0f) return;
    u32 zmn_ord = ordf(zmn);

    u32 W = (u32)(c1 - c0 + 1);
    u32 total = W * (u32)(r1 - r0 + 1);
    u32 m = 0xFFFFFFFFu / W + 1u;   // magic for i/W, i < 2^16

    u64* zb = g_zbuf + b * HW;
    u32 fid = (u32)f;

    for (u32 i = (u32)lane + 32u * (u32)sub; i < total; i += 32u * SPLIT) {
        u32 q = __umulhi(i, m);
        u32 cc = i - q * W;
        int r = r0 + (int)q;
        int c = c0 + (int)cc;
        u64* addr = zb + r * IMG_W + c;
        u32 cur_hi = ((const u32*)addr)[1];
        if (zmn_ord > cur_hi) continue;

        float px = (float)c + 0.5f;
        float py = (float)r + 0.5f;
        float e0 = dx0 * (py - y1) - dy0 * (px - x1);
        float e1 = dx1 * (py - y2) - dy1 * (px - x2);
        float e2 = dx2 * (py - y0) - dy2 * (px - x0);
        float area = (e0 + e1) + e2;
        if (fabsf(area) <= EPSF) continue;
        float s = area > 0.f ? 1.f : -1.f;
        if (e0 * s < 0.f || e1 * s < 0.f || e2 * s < 0.f) continue;

        float num = e0 * z0 + e1 * z1;
        num += e2 * z2;
        float z = num / area;     // exact division: matches reference rounding
        if (!(z >= -1.f && z <= 1.f)) continue;

        u32 uz = ordf(z);
        if (uz > cur_hi) continue;
        u64 key = ((u64)uz << 32) | fid;
        atomicMin(addr, key);
    }
}

// ---------------------------------------------------------------------------
// Kernel 3: per-pixel perspective-correct shade + bilinear texture sample
// [R8 verbatim]
// ---------------------------------------------------------------------------
__global__ void k_shade(const float* __restrict__ uv_map,
                        const int* __restrict__ faces,
                        const float* __restrict__ texture,
                        float* __restrict__ out,
                        int N, int F, int TH, int TW, int B) {
    int p = blockIdx.x * blockDim.x + threadIdx.x;
    if (p >= B * HW) return;
    int b = p / HW;
    int rc = p - b * HW;
    int r = rc / IMG_W;
    int c = rc - r * IMG_W;

    float o0 = 0.f, o1 = 0.f, o2 = 0.f;
    u64 key = g_zbuf[p];
    if (key != 0xFFFFFFFFFFFFFFFFull) {
        int f = (int)(u32)(key & 0xFFFFFFFFull);
        int i0 = faces[3 * f + 0];
        int i1 = faces[3 * f + 1];
        int i2 = faces[3 * f + 2];
        float4 v0 = g_verts[b * N + i0];
        float4 v1 = g_verts[b * N + i1];
        float4 v2 = g_verts[b * N + i2];

        float px = (float)c + 0.5f, py = (float)r + 0.5f;
        float e0 = (v2.x - v1.x) * (py - v1.y) - (v2.y - v1.y) * (px - v1.x);
        float e1 = (v0.x - v2.x) * (py - v2.y) - (v0.y - v2.y) * (px - v2.x);
        float e2 = (v1.x - v0.x) * (py - v0.y) - (v1.y - v0.y) * (px - v0.x);

        float bw0 = e0 / v0.w, bw1 = e1 / v1.w, bw2 = e2 / v2.w;
        float denom = (bw0 + bw1) + bw2;
        if (fabsf(denom) <= EPSF) denom = 1.f;
        float pc0 = bw0 / denom, pc1 = bw1 / denom, pc2 = bw2 / denom;

        float mask = (pc0 + pc1) + pc2;  // color channel 0 is all-ones

        const float* uvb = uv_map + (size_t)b * N * 2;
        float u = pc0 * __ldg(uvb + i0 * 2 + 0) + pc1 * __ldg(uvb + i1 * 2 + 0) + pc2 * __ldg(uvb + i2 * 2 + 0);
        float v = pc0 * __ldg(uvb + i0 * 2 + 1) + pc1 * __ldg(uvb + i1 * 2 + 1) + pc2 * __ldg(uvb + i2 * 2 + 1);

        float fyf = fminf(fmaxf(v, 0.f), 1.f) * (float)TH;
        float fxf = fminf(fmaxf(u, 0.f), 1.f) * (float)TW;
        float fly = floorf(fyf), flx = floorf(fxf);
        float fry = fyf - fly, frx = fxf - flx;
        int iy = (int)fly, ix = (int)flx;
        int iy0 = min(max(iy, 0), TH - 1);
        int iy1 = min(max(iy + 1, 0), TH - 1);
        int ix0 = min(max(ix, 0), TW - 1);
        int ix1 = min(max(ix + 1, 0), TW - 1);

        const float* T = texture + (size_t)b * TH * TW * 3;
        const float* tl = T + ((size_t)iy0 * TW + ix0) * 3;
        const float* tr = T + ((size_t)iy0 * TW + ix1) * 3;
        const float* bl = T + ((size_t)iy1 * TW + ix0) * 3;
        const float* br = T + ((size_t)iy1 * TW + ix1) * 3;

        float wtl = (1.f - frx) * (1.f - fry);
        float wtr = frx * (1.f - fry);
        float wbl = (1.f - frx) * fry;
        float wbr = frx * fry;

        o0 = (__ldg(tl + 0) * wtl + __ldg(tr + 0) * wtr + __ldg(bl + 0) * wbl + __ldg(br + 0) * wbr) * mask;
        o1 = (__ldg(tl + 1) * wtl + __ldg(tr + 1) * wtr + __ldg(bl + 1) * wbl + __ldg(br + 1) * wbr) * mask;
        o2 = (__ldg(tl + 2) * wtl + __ldg(tr + 2) * wtr + __ldg(bl + 2) * wbl + __ldg(br + 2) * wbr) * mask;
    }
    float* op = out + (size_t)p * 3;
    op[0] = o0;
    op[1] = o1;
    op[2] = o2;
}

// ---------------------------------------------------------------------------
// Launch: 3 nodes — persistent prologue, full-occupancy raster, shade.
// ---------------------------------------------------------------------------
extern "C" void kernel_launch(void* const* d_in, const int* in_sizes, int n_in,
                              void* d_out, int out_size) {
    const float* vertices = (const float*)d_in[0];
    const float* uv_map   = (const float*)d_in[1];
    const int*   faces    = (const int*)d_in[2];
    const float* texture  = (const float*)d_in[3];
    const float* poses    = (const float*)d_in[4];
    float* out = (float*)d_out;

    int B = in_sizes[4] / 16;
    int N = in_sizes[0] / (3 * B);
    int F = in_sizes[2] / 3;
    long texel = (long)in_sizes[3] / (3L * B);
    int TH = (int)(sqrt((double)texel) + 0.5);
    int TW = TH;

    int npix = B * HW;
    int nf = B * F;

    k_pre<<<PRE_NBLK, PRE_NTHR>>>(vertices, poses, faces, N, F, B);
    int nwarps = nf * SPLIT;
    k_raster<<<(nwarps * 32 + 255) / 256, 256>>>(faces, N, F, B);
    k_shade<<<(npix + 255) / 256, 256>>>(uv_map, faces, texture, out, N, F, TH, TW, B);
}

// round 16
// speedup vs baseline: 1.4843x; 1.0245x over previous
#include <cuda_runtime.h>
#include <cstdint>
#include <math.h>

#define IMG_H 128
#define IMG_W 128
#define HW (IMG_H * IMG_W)
#define B_MAX 4
#define F_MAX 8192
#define N_MAX 4096
#define EPSF 1e-9f
#define BINS 4096

#define PRE_NBLK 256
#define PRE_NTHR 256
#define SPLIT 2

typedef unsigned long long u64;
typedef unsigned int u32;

// Scratch (allocation-free: __device__ globals)
__device__ float4 g_verts[B_MAX * N_MAX];     // (sx, sy, sz, w)
__device__ u64 g_zbuf[B_MAX * HW];            // (ordered_z << 32) | face_id
__device__ u32 g_fz[B_MAX * F_MAX];           // per-(b,f) ordered-encoded zmin
__device__ u32 g_fbin[B_MAX * F_MAX];         // per-(b,f) depth bin
__device__ u32 g_sorted[B_MAX * F_MAX];       // (b*F+f) sorted front-to-back
__device__ u32 g_hist[BINS];
__device__ u32 g_cursor[BINS];
__device__ u32 g_zlo_u, g_zhi_u;              // ordered-encoded global zmin range

// Grid barrier state (monotonic generation; survives graph replays)
__device__ u32 g_gen = 0;
__device__ u32 g_cnt = 0;

__device__ __forceinline__ u32 ordf(float z) {
    u32 uz = __float_as_uint(z);
    return (uz & 0x80000000u) ? ~uz : (uz | 0x80000000u);
}

// Grid-wide barrier for k_pre (PRE_NBLK blocks, all resident: 256 <= 148*2).
__device__ __forceinline__ void gbar() {
    __threadfence();
    __syncthreads();
    if (threadIdx.x == 0) {
        u32 gen = atomicAdd(&g_gen, 0u);
        if (atomicAdd(&g_cnt, 1u) + 1u == (u32)PRE_NBLK) {
            atomicExch(&g_cnt, 0u);
            __threadfence();
            atomicAdd(&g_gen, 1u);
        } else {
            while (atomicAdd(&g_gen, 0u) == gen) __nanosleep(32);
        }
    }
    __syncthreads();
}

// ---------------------------------------------------------------------------
// Kernel 1 (persistent, cheap phases): clear + transform + facez + hist +
// scan + scatter. Low occupancy is fine here — total work is tiny.
// ---------------------------------------------------------------------------
__global__ __launch_bounds__(PRE_NTHR, 2)
void k_pre(const float* __restrict__ vertices,
           const float* __restrict__ poses,
           const int* __restrict__ faces,
           int N, int F, int B) {
    const int gid = blockIdx.x * PRE_NTHR + threadIdx.x;
    const int nth = PRE_NBLK * PRE_NTHR;
    const int npix = B * HW;
    const int nf = B * F;

    // ---- Phase 1: clear + vertex transform ----
    for (int i = gid; i < npix; i += nth) g_zbuf[i] = 0xFFFFFFFFFFFFFFFFull;
    for (int i = gid; i < BINS; i += nth) g_hist[i] = 0;
    if (gid == 0) { g_zlo_u = 0xFFFFFFFFu; g_zhi_u = 0u; }

    {
        const double NEAR = 0.1, FAR = 10.0, FOCAL = 140.0;
        const double RIGHT = (IMG_W - 1.0) / 2.0 * NEAR / FOCAL;
        const double TOP = RIGHT * ((double)IMG_H / (double)IMG_W);
        const float p00 = (float)(NEAR / RIGHT);
        const float p11 = (float)(NEAR / TOP);
        const float p22 = (float)(-(FAR + NEAR) / (FAR - NEAR));
        const float p32 = (float)(-2.0 * FAR * NEAR / (FAR - NEAR));

        for (int i = gid; i < B * N; i += nth) {
            int b = i / N;
            int v = i - b * N;
            const float* P = poses + b * 16;
            float C[4][4];
            const float sgn[3] = {1.f, -1.f, -1.f};
#pragma unroll
            for (int r = 0; r < 3; ++r)
#pragma unroll
                for (int c = 0; c < 3; ++c)
                    C[r][c] = sgn[r] * P[r * 4 + c];
            C[0][3] = P[3];
            C[1][3] = -P[7];
            C[2][3] = -P[11];
#pragma unroll
            for (int c = 0; c < 4; ++c) C[3][c] = P[12 + c];

            const float* vp = vertices + ((size_t)b * N + v) * 3;
            float x = vp[0], y = vp[1], z = vp[2];
            float v0 = x * C[0][0] + y * C[0][1] + z * C[0][2] + C[0][3];
            float v1 = x * C[1][0] + y * C[1][1] + z * C[1][2] + C[1][3];
            float v2 = x * C[2][0] + y * C[2][1] + z * C[2][2] + C[2][3];
            float v3 = x * C[3][0] + y * C[3][1] + z * C[3][2] + C[3][3];
            float cx = v0 * p00;
            float cy = v1 * p11;
            float cz = v2 * p22 + v3 * p32;
            float cw = -v2;
            float sx = (cx / cw * 0.5f + 0.5f) * (float)IMG_W;
            float sy = (0.5f - cy / cw * 0.5f) * (float)IMG_H;
            float sz = cz / cw;
            g_verts[b * N + v] = make_float4(sx, sy, sz, cw);
        }
    }
    gbar();

    // ---- Phase 2: per-face zmin + global range ----
    // Warp-reduce (REDUX) before the global atomic: 2 atomics per WARP
    // instead of per thread — kills the single-address serialization
    // (~0.854 cyc/lane x 65K ops ~= 25us) that dominated k_pre.
    // Identity values for invalid lanes keep the range bit-identical.
    for (int idx = gid; idx < nf; idx += nth) {
        int b = idx / F;
        int f = idx - b * F;
        int i0 = faces[3 * f + 0];
        int i1 = faces[3 * f + 1];
        int i2 = faces[3 * f + 2];
        const float4* vb = g_verts + b * N;
        float4 v0, v1, v2;
        v0.z = __ldcg(&vb[i0].z); v0.w = __ldcg(&vb[i0].w);
        v1.z = __ldcg(&vb[i1].z); v1.w = __ldcg(&vb[i1].w);
        v2.z = __ldcg(&vb[i2].z); v2.w = __ldcg(&vb[i2].w);
        bool valid = (v0.w > 1e-6f && v1.w > 1e-6f && v2.w > 1e-6f);
        u32 e = 0xFFFFFFFFu;
        if (valid) {
            float zmn = fminf(v0.z, fminf(v1.z, v2.z));
            e = ordf(zmn);
        }
        u32 mask = __activemask();
        u32 emin = __reduce_min_sync(mask, valid ? e : 0xFFFFFFFFu);
        u32 emax = __reduce_max_sync(mask, valid ? e : 0u);
        u32 leader = __ffs(mask) - 1u;
        if ((threadIdx.x & 31u) == leader) {
            atomicMin(&g_zlo_u, emin);
            atomicMax(&g_zhi_u, emax);
        }
        g_fz[idx] = e;
    }
    gbar();

    // ---- Phase 3: histogram (adaptive range) ----
    {
        u32 lo = __ldcg(&g_zlo_u), hi = __ldcg(&g_zhi_u);
        for (int idx = gid; idx < nf; idx += nth) {
            u32 e = g_fz[idx];          // own write (same mapping)
            u32 bin;
            if (e == 0xFFFFFFFFu) bin = BINS - 1;
            else if (hi <= lo) bin = 0;
            else {
                u64 d = (u64)(e - lo);
                bin = (u32)((d * (u64)(BINS - 1)) / (u64)(hi - lo));
                if (bin > BINS - 2) bin = BINS - 2;
            }
            g_fbin[idx] = bin;
            atomicAdd(&g_hist[bin], 1u);
        }
    }
    gbar();

    // ---- Phase 4: exclusive scan over BINS (block 0) ----
    __shared__ u32 sh[PRE_NTHR];
    if (blockIdx.x == 0) {
        int t = threadIdx.x;
        const int PER = BINS / PRE_NTHR;   // 16
        u32 s = 0;
#pragma unroll
        for (int j = 0; j < PER; ++j) s += __ldcg(&g_hist[t * PER + j]);
        sh[t] = s;
        __syncthreads();
        for (int d = 1; d < PRE_NTHR; d <<= 1) {
            u32 v = sh[t];
            u32 w = (t >= d) ? sh[t - d] : 0u;
            __syncthreads();
            sh[t] = v + w;
            __syncthreads();
        }
        u32 run = (t == 0) ? 0u : sh[t - 1];
#pragma unroll
        for (int j = 0; j < PER; ++j) {
            u32 hv = __ldcg(&g_hist[t * PER + j]);
            g_cursor[t * PER + j] = run;
            run += hv;
        }
    }
    gbar();

    // ---- Phase 5: scatter into sorted order (cursor via L2 atomics) ----
    for (int idx = gid; idx < nf; idx += nth) {
        u32 pos = atomicAdd(&g_cursor[g_fbin[idx]], 1u);
        g_sorted[pos] = (u32)idx;
    }
}

// ---------------------------------------------------------------------------
// Kernel 2: raster, front-to-back order, 2 warps/face, 32-bit early-Z prune.
// [R8 verbatim — full-occupancy standalone launch]
// ---------------------------------------------------------------------------
__global__ void k_raster(const int* __restrict__ faces, int N, int F, int B) {
    int gw = (blockIdx.x * blockDim.x + threadIdx.x) >> 5;
    int lane = threadIdx.x & 31;
    int slot = gw >> 1;
    int sub = gw & 1;
    if (slot >= B * F) return;
    int idx = (int)g_sorted[slot];
    int b = idx / F;
    int f = idx - b * F;

    int i0 = faces[3 * f + 0];
    int i1 = faces[3 * f + 1];
    int i2 = faces[3 * f + 2];
    float4 v0 = g_verts[b * N + i0];
    float4 v1 = g_verts[b * N + i1];
    float4 v2 = g_verts[b * N + i2];

    if (!(v0.w > 1e-6f && v1.w > 1e-6f && v2.w > 1e-6f)) return;

    float x0 = v0.x, y0 = v0.y, x1 = v1.x, y1 = v1.y, x2 = v2.x, y2 = v2.y;

    float minx = fminf(x0, fminf(x1, x2));
    float maxx = fmaxf(x0, fmaxf(x1, x2));
    float miny = fminf(y0, fminf(y1, y2));
    float maxy = fmaxf(y0, fmaxf(y1, y2));

    int c0 = max(0, (int)floorf(minx - 0.5f));
    int c1 = min(IMG_W - 1, (int)ceilf(maxx - 0.5f));
    int r0 = max(0, (int)floorf(miny - 0.5f));
    int r1 = min(IMG_H - 1, (int)ceilf(maxy - 0.5f));
    if (c1 < c0 || r1 < r0) return;

    float dx0 = x2 - x1, dy0 = y2 - y1;
    float dx1 = x0 - x2, dy1 = y0 - y2;
    float dx2 = x1 - x0, dy2 = y1 - y0;
    float z0 = v0.z, z1 = v1.z, z2 = v2.z;

    float zmn = fminf(z0, fminf(z1, z2)) - 1e-5f;
    if (zmn > 1.0f) return;
    u32 zmn_ord = ordf(zmn);

    u32 W = (u32)(c1 - c0 + 1);
    u32 total = W * (u32)(r1 - r0 + 1);
    u32 m = 0xFFFFFFFFu / W + 1u;   // magic for i/W, i < 2^16

    u64* zb = g_zbuf + b * HW;
    u32 fid = (u32)f;

    for (u32 i = (u32)lane + 32u * (u32)sub; i < total; i += 32u * SPLIT) {
        u32 q = __umulhi(i, m);
        u32 cc = i - q * W;
        int r = r0 + (int)q;
        int c = c0 + (int)cc;
        u64* addr = zb + r * IMG_W + c;
        u32 cur_hi = ((const u32*)addr)[1];
        if (zmn_ord > cur_hi) continue;

        float px = (float)c + 0.5f;
        float py = (float)r + 0.5f;
        float e0 = dx0 * (py - y1) - dy0 * (px - x1);
        float e1 = dx1 * (py - y2) - dy1 * (px - x2);
        float e2 = dx2 * (py - y0) - dy2 * (px - x0);
        float area = (e0 + e1) + e2;
        if (fabsf(area) <= EPSF) continue;
        float s = area > 0.f ? 1.f : -1.f;
        if (e0 * s < 0.f || e1 * s < 0.f || e2 * s < 0.f) continue;

        float num = e0 * z0 + e1 * z1;
        num += e2 * z2;
        float z = num / area;     // exact division: matches reference rounding
        if (!(z >= -1.f && z <= 1.f)) continue;

        u32 uz = ordf(z);
        if (uz > cur_hi) continue;
        u64 key = ((u64)uz << 32) | fid;
        atomicMin(addr, key);
    }
}

// ---------------------------------------------------------------------------
// Kernel 3: per-pixel perspective-correct shade + bilinear texture sample
// [R8 verbatim]
// ---------------------------------------------------------------------------
__global__ void k_shade(const float* __restrict__ uv_map,
                        const int* __restrict__ faces,
                        const float* __restrict__ texture,
                        float* __restrict__ out,
                        int N, int F, int TH, int TW, int B) {
    int p = blockIdx.x * blockDim.x + threadIdx.x;
    if (p >= B * HW) return;
    int b = p / HW;
    int rc = p - b * HW;
    int r = rc / IMG_W;
    int c = rc - r * IMG_W;

    float o0 = 0.f, o1 = 0.f, o2 = 0.f;
    u64 key = g_zbuf[p];
    if (key != 0xFFFFFFFFFFFFFFFFull) {
        int f = (int)(u32)(key & 0xFFFFFFFFull);
        int i0 = faces[3 * f + 0];
        int i1 = faces[3 * f + 1];
        int i2 = faces[3 * f + 2];
        float4 v0 = g_verts[b * N + i0];
        float4 v1 = g_verts[b * N + i1];
        float4 v2 = g_verts[b * N + i2];

        float px = (float)c + 0.5f, py = (float)r + 0.5f;
        float e0 = (v2.x - v1.x) * (py - v1.y) - (v2.y - v1.y) * (px - v1.x);
        float e1 = (v0.x - v2.x) * (py - v2.y) - (v0.y - v2.y) * (px - v2.x);
        float e2 = (v1.x - v0.x) * (py - v0.y) - (v1.y - v0.y) * (px - v0.x);

        float bw0 = e0 / v0.w, bw1 = e1 / v1.w, bw2 = e2 / v2.w;
        float denom = (bw0 + bw1) + bw2;
        if (fabsf(denom) <= EPSF) denom = 1.f;
        float pc0 = bw0 / denom, pc1 = bw1 / denom, pc2 = bw2 / denom;

        float mask = (pc0 + pc1) + pc2;  // color channel 0 is all-ones

        const float* uvb = uv_map + (size_t)b * N * 2;
        float u = pc0 * __ldg(uvb + i0 * 2 + 0) + pc1 * __ldg(uvb + i1 * 2 + 0) + pc2 * __ldg(uvb + i2 * 2 + 0);
        float v = pc0 * __ldg(uvb + i0 * 2 + 1) + pc1 * __ldg(uvb + i1 * 2 + 1) + pc2 * __ldg(uvb + i2 * 2 + 1);

        float fyf = fminf(fmaxf(v, 0.f), 1.f) * (float)TH;
        float fxf = fminf(fmaxf(u, 0.f), 1.f) * (float)TW;
        float fly = floorf(fyf), flx = floorf(fxf);
        float fry = fyf - fly, frx = fxf - flx;
        int iy = (int)fly, ix = (int)flx;
        int iy0 = min(max(iy, 0), TH - 1);
        int iy1 = min(max(iy + 1, 0), TH - 1);
        int ix0 = min(max(ix, 0), TW - 1);
        int ix1 = min(max(ix + 1, 0), TW - 1);

        const float* T = texture + (size_t)b * TH * TW * 3;
        const float* tl = T + ((size_t)iy0 * TW + ix0) * 3;
        const float* tr = T + ((size_t)iy0 * TW + ix1) * 3;
        const float* bl = T + ((size_t)iy1 * TW + ix0) * 3;
        const float* br = T + ((size_t)iy1 * TW + ix1) * 3;

        float wtl = (1.f - frx) * (1.f - fry);
        float wtr = frx * (1.f - fry);
        float wbl = (1.f - frx) * fry;
        float wbr = frx * fry;

        o0 = (__ldg(tl + 0) * wtl + __ldg(tr + 0) * wtr + __ldg(bl + 0) * wbl + __ldg(br + 0) * wbr) * mask;
        o1 = (__ldg(tl + 1) * wtl + __ldg(tr + 1) * wtr + __ldg(bl + 1) * wbl + __ldg(br + 1) * wbr) * mask;
        o2 = (__ldg(tl + 2) * wtl + __ldg(tr + 2) * wtr + __ldg(bl + 2) * wbl + __ldg(br + 2) * wbr) * mask;
    }
    float* op = out + (size_t)p * 3;
    op[0] = o0;
    op[1] = o1;
    op[2] = o2;
}

// ---------------------------------------------------------------------------
// Launch: 3 nodes — persistent prologue, full-occupancy raster, shade.
// ---------------------------------------------------------------------------
extern "C" void kernel_launch(void* const* d_in, const int* in_sizes, int n_in,
                              void* d_out, int out_size) {
    const float* vertices = (const float*)d_in[0];
    const float* uv_map   = (const float*)d_in[1];
    const int*   faces    = (const int*)d_in[2];
    const float* texture  = (const float*)d_in[3];
    const float* poses    = (const float*)d_in[4];
    float* out = (float*)d_out;

    int B = in_sizes[4] / 16;
    int N = in_sizes[0] / (3 * B);
    int F = in_sizes[2] / 3;
    long texel = (long)in_sizes[3] / (3L * B);
    int TH = (int)(sqrt((double)texel) + 0.5);
    int TW = TH;

    int npix = B * HW;
    int nf = B * F;

    k_pre<<<PRE_NBLK, PRE_NTHR>>>(vertices, poses, faces, N, F, B);
    int nwarps = nf * SPLIT;
    k_raster<<<(nwarps * 32 + 255) / 256, 256>>>(faces, N, F, B);
    k_shade<<<(npix + 255) / 256, 256>>>(uv_map, faces, texture, out, N, F, TH, TW, B);
}